// round 9
// baseline (speedup 1.0000x reference)
#include <cuda_runtime.h>
#include <cuda_bf16.h>
#include <cstdint>

// Problem constants: B=8,H=64,Wd=128 -> NROWS=65536, D=272, NC=19, P=524288, NI=4096
#define D_FEAT    272
#define NC_OUT    19
#define NC_PAD    20
#define NROWS_MAX 65536
#define NI_MAX    4096

__device__ __align__(16) float g_proj[NROWS_MAX * NC_PAD];   // 5.24 MB, L2-resident
__device__ int g_off[NI_MAX + 1];

__device__ __forceinline__ void ffma2(unsigned long long& d,
                                      unsigned long long a,
                                      unsigned long long b) {
    asm("fma.rn.f32x2 %0, %1, %2, %0;" : "+l"(d) : "l"(a), "l"(b));
}

// ============================================================
// Kernel 1: fused [projection GEMM] + [segment offsets]
//   proj blocks:   1 row/thread, 128 rows/block, K-chunks of 16,
//                  double-buffered smem X (pre-duplicated f32x2),
//                  W staged in smem, LDS.128 broadcast reads.
//   offset blocks: blockIdx >= projBlocks, int4 boundary scan.
// ============================================================
#define P1_THREADS  128
#define P1_ROWS     128
#define KCHUNK      16
#define NCHUNK      (D_FEAT / KCHUNK)      // 17
#define XS_STRIDE   17                     // ull stride; 17 coprime 32 -> conflict-free
#define OFF_BLOCKS  32

__global__ __launch_bounds__(P1_THREADS)
void proj_and_offsets_kernel(const float4* __restrict__ feats4,  // [NROWS, 68]
                             const float*  __restrict__ Wmat,    // [272, 19]
                             const int*    __restrict__ seg,     // [P] sorted
                             int P, int NI, int nrows, int projBlocks)
{
    const int tid = threadIdx.x;

    // ---------- offset blocks ----------
    if ((int)blockIdx.x >= projBlocks) {
        const int b  = blockIdx.x - projBlocks;
        const int nt = OFF_BLOCKS * P1_THREADS;
        const int G  = P >> 2;
        const int4* seg4 = reinterpret_cast<const int4*>(seg);
        for (int g = b * P1_THREADS + tid; g < G; g += nt) {
            const int4 v = __ldg(&seg4[g]);
            int prev = (g == 0) ? -1 : __ldg(&seg[4 * g - 1]);
            const int i0 = 4 * g;
            int vv[4] = { v.x, v.y, v.z, v.w };
            #pragma unroll
            for (int j = 0; j < 4; ++j) {
                const int cur = vv[j];
                for (int s = prev + 1; s <= cur; ++s) g_off[s] = i0 + j;
                prev = cur;
            }
            if (i0 + 4 == P) {
                for (int s = prev + 1; s <= NI; ++s) g_off[s] = P;
            }
        }
        // scalar tail if P not divisible by 4
        if (b == 0 && tid == 0 && (P & 3)) {
            int prev = (P >= 4 && (P & ~3) > 0) ? __ldg(&seg[(P & ~3) - 1]) : -1;
            for (int i = P & ~3; i < P; ++i) {
                const int cur = __ldg(&seg[i]);
                for (int s = prev + 1; s <= cur; ++s) g_off[s] = i;
                prev = cur;
            }
            for (int s = prev + 1; s <= NI; ++s) g_off[s] = P;
        }
        return;
    }

    // ---------- projection blocks ----------
    __shared__ float wsh[D_FEAT * NC_PAD];                        // 21.8 KB
    __shared__ unsigned long long xs2[2][P1_ROWS * XS_STRIDE];    // 2 x 17.4 KB

    const int rowBase = blockIdx.x * P1_ROWS;
    const int r0 = rowBase + tid;
    const bool v0 = r0 < nrows;

    for (int i = tid; i < D_FEAT * NC_PAD; i += P1_THREADS) {
        const int c = i / NC_PAD, o = i % NC_PAD;
        wsh[i] = (o < NC_OUT) ? Wmat[c * NC_OUT + o] : 0.0f;
    }

    const uint32_t wbase = (uint32_t)__cvta_generic_to_shared(wsh);
    const uint32_t xbase0 = (uint32_t)__cvta_generic_to_shared(&xs2[0][0]);
    const uint32_t xbase1 = (uint32_t)__cvta_generic_to_shared(&xs2[1][0]);

    unsigned long long acc[NC_PAD / 2];
    #pragma unroll
    for (int j = 0; j < NC_PAD / 2; ++j) acc[j] = 0ull;

    // staging geometry: j = tid + t*128, rr = j>>2, qq = j&3 (4 float4/thread/chunk)
    float4 pre[4];
    {
        const int cc = 0;
        #pragma unroll
        for (int t = 0; t < 4; ++t) {
            const int j = tid + t * P1_THREADS;
            const int rr = j >> 2, qq = j & 3;
            const int gr = rowBase + rr;
            pre[t] = (gr < nrows) ? __ldg(&feats4[(long)gr * 68 + (cc >> 2) + qq])
                                  : make_float4(0.f, 0.f, 0.f, 0.f);
        }
    }

    for (int c0 = 0; c0 < NCHUNK; ++c0) {
        unsigned long long* buf = xs2[c0 & 1];
        // store prefetched chunk, duplicated into f32x2 pairs
        #pragma unroll
        for (int t = 0; t < 4; ++t) {
            const int j = tid + t * P1_THREADS;
            const int rr = j >> 2, qq = j & 3;
            unsigned long long p0, p1, p2, p3;
            asm("mov.b64 %0, {%1, %1};" : "=l"(p0) : "f"(pre[t].x));
            asm("mov.b64 %0, {%1, %1};" : "=l"(p1) : "f"(pre[t].y));
            asm("mov.b64 %0, {%1, %1};" : "=l"(p2) : "f"(pre[t].z));
            asm("mov.b64 %0, {%1, %1};" : "=l"(p3) : "f"(pre[t].w));
            unsigned long long* dst = &buf[rr * XS_STRIDE + qq * 4];
            dst[0] = p0; dst[1] = p1; dst[2] = p2; dst[3] = p3;
        }
        __syncthreads();

        // prefetch next chunk (overlaps with compute below)
        if (c0 + 1 < NCHUNK) {
            const int cc = (c0 + 1) * KCHUNK;
            #pragma unroll
            for (int t = 0; t < 4; ++t) {
                const int j = tid + t * P1_THREADS;
                const int rr = j >> 2, qq = j & 3;
                const int gr = rowBase + rr;
                pre[t] = (gr < nrows) ? __ldg(&feats4[(long)gr * 68 + (cc >> 2) + qq])
                                      : make_float4(0.f, 0.f, 0.f, 0.f);
            }
        }

        const uint32_t xb = (c0 & 1) ? xbase1 : xbase0;
        #pragma unroll
        for (int k = 0; k < KCHUNK; ++k) {
            const int c = c0 * KCHUNK + k;
            unsigned long long xp;
            const uint32_t xa = xb + (tid * XS_STRIDE + k) * 8u;
            asm("ld.shared.b64 %0, [%1];" : "=l"(xp) : "r"(xa));
            unsigned long long w[10];
            const uint32_t wa = wbase + (uint32_t)c * (NC_PAD * 4u);
            asm("ld.shared.v2.b64 {%0,%1}, [%2];"    : "=l"(w[0]), "=l"(w[1]) : "r"(wa));
            asm("ld.shared.v2.b64 {%0,%1}, [%2+16];" : "=l"(w[2]), "=l"(w[3]) : "r"(wa));
            asm("ld.shared.v2.b64 {%0,%1}, [%2+32];" : "=l"(w[4]), "=l"(w[5]) : "r"(wa));
            asm("ld.shared.v2.b64 {%0,%1}, [%2+48];" : "=l"(w[6]), "=l"(w[7]) : "r"(wa));
            asm("ld.shared.v2.b64 {%0,%1}, [%2+64];" : "=l"(w[8]), "=l"(w[9]) : "r"(wa));
            #pragma unroll
            for (int j = 0; j < NC_PAD / 2; ++j) ffma2(acc[j], xp, w[j]);
        }
        __syncthreads();
    }

    if (v0) {
        ulonglong2* p = reinterpret_cast<ulonglong2*>(g_proj + (long)r0 * NC_PAD);
        p[0] = make_ulonglong2(acc[0], acc[1]);
        p[1] = make_ulonglong2(acc[2], acc[3]);
        p[2] = make_ulonglong2(acc[4], acc[5]);
        p[3] = make_ulonglong2(acc[6], acc[7]);
        p[4] = make_ulonglong2(acc[8], acc[9]);
    }
}

// ============================================================
// Kernel 2: pool + bias + sigmoid. 25 point-lanes x 5 quads.
// ============================================================
#define P2_THREADS 128
#define NLANES     25

__global__ __launch_bounds__(P2_THREADS)
void pool_head_kernel(const int* __restrict__ point_idx,
                      const float* __restrict__ bias,
                      float* __restrict__ out)     // [NI, 19]
{
    const int s   = blockIdx.x;
    const int tid = threadIdx.x;

    __shared__ int sh_range[2];
    __shared__ float4 red[NLANES][5];

    if (tid < 2) sh_range[tid] = g_off[s + tid];
    __syncthreads();
    const int start = sh_range[0];
    const int end   = sh_range[1];

    const float4* proj4 = reinterpret_cast<const float4*>(g_proj);

    const int lane = tid / 5;   // 0..24 (tid<125)
    const int quad = tid % 5;   // 0..4

    float4 acc = make_float4(0.f, 0.f, 0.f, 0.f);

    if (lane < NLANES) {
        int i = start + lane;
        for (; i + NLANES < end; i += 2 * NLANES) {
            const long rA = __ldg(&point_idx[i]);
            const long rB = __ldg(&point_idx[i + NLANES]);
            const float4 vA = __ldg(&proj4[rA * 5 + quad]);
            const float4 vB = __ldg(&proj4[rB * 5 + quad]);
            acc.x += vA.x + vB.x; acc.y += vA.y + vB.y;
            acc.z += vA.z + vB.z; acc.w += vA.w + vB.w;
        }
        if (i < end) {
            const long r = __ldg(&point_idx[i]);
            const float4 v = __ldg(&proj4[r * 5 + quad]);
            acc.x += v.x; acc.y += v.y; acc.z += v.z; acc.w += v.w;
        }
        red[lane][quad] = acc;
    }
    __syncthreads();

    if (tid < NC_OUT) {
        const float* rf = reinterpret_cast<const float*>(red);
        float v = 0.0f;
        #pragma unroll
        for (int l = 0; l < NLANES; ++l) v += rf[l * 20 + tid];
        const float inv = 1.0f / (float)max(end - start, 1);
        const float o = v * inv + __ldg(&bias[tid]);
        out[s * NC_OUT + tid] = 1.0f / (1.0f + expf(-o));
    }
}

// ============================================================
extern "C" void kernel_launch(void* const* d_in, const int* in_sizes, int n_in,
                              void* d_out, int out_size)
{
    // order: class_capsules, W, b, point_idx, segment_ids, num_segments
    const float4* feats4    = (const float4*)d_in[0];
    const float*  Wmat      = (const float*) d_in[1];
    const float*  bias      = (const float*) d_in[2];
    const int*    point_idx = (const int*)   d_in[3];
    const int*    seg_ids   = (const int*)   d_in[4];
    const int     P         = in_sizes[3];
    const int     nrows     = in_sizes[0] / D_FEAT;
    const int     NI        = out_size / NC_OUT;
    float* out = (float*)d_out;

    const int projBlocks = (nrows + P1_ROWS - 1) / P1_ROWS;

    proj_and_offsets_kernel<<<projBlocks + OFF_BLOCKS, P1_THREADS>>>(
        feats4, Wmat, seg_ids, P, NI, nrows, projBlocks);

    pool_head_kernel<<<NI, P2_THREADS>>>(point_idx, bias, out);
}

// round 11
// speedup vs baseline: 1.4817x; 1.4817x over previous
#include <cuda_runtime.h>
#include <cuda_bf16.h>
#include <cstdint>

// Problem constants: B=8,H=64,Wd=128 -> NROWS=65536, D=272, NC=19, P=524288, NI=4096
#define D_FEAT    272
#define NC_OUT    19
#define NC_PAD    20
#define NROWS_MAX 65536
#define NI_MAX    4096

__device__ __align__(16) float g_proj[NROWS_MAX * NC_PAD];   // 5.24 MB, L2-resident
__device__ int g_off[NI_MAX + 1];

__device__ __forceinline__ void ffma2(unsigned long long& d,
                                      unsigned long long a,
                                      unsigned long long b) {
    asm("fma.rn.f32x2 %0, %1, %2, %0;" : "+l"(d) : "l"(a), "l"(b));
}
__device__ __forceinline__ unsigned long long packdup(float x) {
    unsigned long long r;
    asm("mov.b64 %0, {%1, %1};" : "=l"(r) : "f"(x));
    return r;
}

// ============================================================
// Kernel 1: fused [projection GEMM] + [segment offsets]
//  proj blocks: 128 thr, 1 row/thread, K-chunks of 32 (tail 16),
//    X staged as plain f32 (stride 33 -> conflict-free), 128B-
//    contiguous staging runs (nL=4), W smem, f32x2 FMA pairs.
//  offset blocks: blockIdx >= projBlocks, int4 boundary scan.
// ============================================================
#define P1_THREADS  128
#define P1_ROWS     128
#define KCH         32
#define NFULL       8                     // 8*32 = 256, tail 16
#define XSTRIDE     33                    // floats; lane stride 33%32=1
#define OFF_BLOCKS  64

__global__ __launch_bounds__(P1_THREADS)
void proj_and_offsets_kernel(const float4* __restrict__ feats4,  // [NROWS, 68]
                             const float*  __restrict__ Wmat,    // [272, 19]
                             const int*    __restrict__ seg,     // [P] sorted
                             int P, int NI, int nrows, int projBlocks)
{
    const int tid = threadIdx.x;

    // ---------------- offset blocks ----------------
    if ((int)blockIdx.x >= projBlocks) {
        const int b  = blockIdx.x - projBlocks;
        const int nt = OFF_BLOCKS * P1_THREADS;
        const int G  = P >> 2;
        const int4* seg4 = reinterpret_cast<const int4*>(seg);
        for (int g = b * P1_THREADS + tid; g < G; g += nt) {
            const int4 v = __ldg(&seg4[g]);
            int prev = (g == 0) ? -1 : __ldg(&seg[4 * g - 1]);
            const int i0 = 4 * g;
            const int vv[4] = { v.x, v.y, v.z, v.w };
            #pragma unroll
            for (int j = 0; j < 4; ++j) {
                const int cur = vv[j];
                for (int s = prev + 1; s <= cur; ++s) g_off[s] = i0 + j;
                prev = cur;
            }
            if (i0 + 4 == P) {
                for (int s = prev + 1; s <= NI; ++s) g_off[s] = P;
            }
        }
        if (b == 0 && tid == 0 && (P & 3)) {
            int prev = ((P & ~3) > 0) ? __ldg(&seg[(P & ~3) - 1]) : -1;
            for (int i = P & ~3; i < P; ++i) {
                const int cur = __ldg(&seg[i]);
                for (int s = prev + 1; s <= cur; ++s) g_off[s] = i;
                prev = cur;
            }
            for (int s = prev + 1; s <= NI; ++s) g_off[s] = P;
        }
        return;
    }

    // ---------------- projection blocks ----------------
    __shared__ float wsh[D_FEAT * NC_PAD];          // 21.8 KB
    __shared__ float xs[P1_ROWS * XSTRIDE];         // 16.9 KB

    const int rowBase = blockIdx.x * P1_ROWS;
    const int r0 = rowBase + tid;
    const bool v0 = r0 < nrows;

    for (int i = tid; i < D_FEAT * NC_PAD; i += P1_THREADS) {
        const int c = i / NC_PAD, o = i % NC_PAD;
        wsh[i] = (o < NC_OUT) ? Wmat[c * NC_OUT + o] : 0.0f;
    }

    const uint32_t wbase = (uint32_t)__cvta_generic_to_shared(wsh);

    unsigned long long acc[NC_PAD / 2];
    #pragma unroll
    for (int j = 0; j < NC_PAD / 2; ++j) acc[j] = 0ull;

    for (int c0 = 0; c0 <= NFULL; ++c0) {
        const int cbase   = c0 * KCH;                    // channel base
        const int kf      = (c0 < NFULL) ? (KCH/4) : 4;  // float4s per row this chunk
        __syncthreads();
        // stage: 8 (or 4) float4 per row; 8 threads/row -> 128B contiguous runs
        for (int j = tid; j < P1_ROWS * kf; j += P1_THREADS) {
            const int rr = j / kf;
            const int qq = j - rr * kf;
            const int gr = rowBase + rr;
            float4 val = make_float4(0.f, 0.f, 0.f, 0.f);
            if (gr < nrows) val = __ldg(&feats4[(long)gr * 68 + (cbase >> 2) + qq]);
            float* dst = &xs[rr * XSTRIDE + qq * 4];
            dst[0] = val.x; dst[1] = val.y; dst[2] = val.z; dst[3] = val.w;
        }
        __syncthreads();

        const int klen = (c0 < NFULL) ? KCH : (D_FEAT - NFULL * KCH);   // 32 or 16
        #pragma unroll 16
        for (int k = 0; k < klen; ++k) {
            const unsigned long long xp = packdup(xs[tid * XSTRIDE + k]);
            unsigned long long w[10];
            const uint32_t wa = wbase + (uint32_t)(cbase + k) * (NC_PAD * 4u);
            asm("ld.shared.v2.b64 {%0,%1}, [%2];"    : "=l"(w[0]), "=l"(w[1]) : "r"(wa));
            asm("ld.shared.v2.b64 {%0,%1}, [%2+16];" : "=l"(w[2]), "=l"(w[3]) : "r"(wa));
            asm("ld.shared.v2.b64 {%0,%1}, [%2+32];" : "=l"(w[4]), "=l"(w[5]) : "r"(wa));
            asm("ld.shared.v2.b64 {%0,%1}, [%2+48];" : "=l"(w[6]), "=l"(w[7]) : "r"(wa));
            asm("ld.shared.v2.b64 {%0,%1}, [%2+64];" : "=l"(w[8]), "=l"(w[9]) : "r"(wa));
            #pragma unroll
            for (int j = 0; j < NC_PAD / 2; ++j) ffma2(acc[j], xp, w[j]);
        }
    }

    if (v0) {
        ulonglong2* p = reinterpret_cast<ulonglong2*>(g_proj + (long)r0 * NC_PAD);
        p[0] = make_ulonglong2(acc[0], acc[1]);
        p[1] = make_ulonglong2(acc[2], acc[3]);
        p[2] = make_ulonglong2(acc[4], acc[5]);
        p[3] = make_ulonglong2(acc[6], acc[7]);
        p[4] = make_ulonglong2(acc[8], acc[9]);
    }
}

// ============================================================
// Kernel 2: pool + bias + sigmoid.
// 160 threads = 5 warps; warp w owns float4-quad w, lanes = points.
// idx loads coalesced; 1 LDG.128 per point-quad; butterfly reduce.
// ============================================================
#define P2_THREADS 160

__global__ __launch_bounds__(P2_THREADS)
void pool_head_kernel(const int* __restrict__ point_idx,
                      const float* __restrict__ bias,
                      float* __restrict__ out)     // [NI, 19]
{
    const int s    = blockIdx.x;
    const int tid  = threadIdx.x;
    const int w    = tid >> 5;          // quad 0..4
    const int lane = tid & 31;

    __shared__ int sh_range[2];
    __shared__ float4 pooled4[5];

    if (tid < 2) sh_range[tid] = g_off[s + tid];
    __syncthreads();
    const int start = sh_range[0];
    const int end   = sh_range[1];

    const float4* proj4 = reinterpret_cast<const float4*>(g_proj);

    float4 acc = make_float4(0.f, 0.f, 0.f, 0.f);

    int i = start + lane;
    for (; i + 32 < end; i += 64) {
        const int rA = __ldg(&point_idx[i]);
        const int rB = __ldg(&point_idx[i + 32]);
        const float4 vA = __ldg(&proj4[(long)rA * 5 + w]);
        const float4 vB = __ldg(&proj4[(long)rB * 5 + w]);
        acc.x += vA.x + vB.x; acc.y += vA.y + vB.y;
        acc.z += vA.z + vB.z; acc.w += vA.w + vB.w;
    }
    if (i < end) {
        const int r = __ldg(&point_idx[i]);
        const float4 v = __ldg(&proj4[(long)r * 5 + w]);
        acc.x += v.x; acc.y += v.y; acc.z += v.z; acc.w += v.w;
    }

    // butterfly reduce within each warp
    #pragma unroll
    for (int d = 16; d; d >>= 1) {
        acc.x += __shfl_xor_sync(0xFFFFFFFFu, acc.x, d);
        acc.y += __shfl_xor_sync(0xFFFFFFFFu, acc.y, d);
        acc.z += __shfl_xor_sync(0xFFFFFFFFu, acc.z, d);
        acc.w += __shfl_xor_sync(0xFFFFFFFFu, acc.w, d);
    }
    if (lane == 0) pooled4[w] = acc;
    __syncthreads();

    if (tid < NC_OUT) {
        const float* pf = reinterpret_cast<const float*>(pooled4);
        const float inv = 1.0f / (float)max(end - start, 1);
        const float o = pf[tid] * inv + __ldg(&bias[tid]);
        out[s * NC_OUT + tid] = 1.0f / (1.0f + expf(-o));
    }
}

// ============================================================
extern "C" void kernel_launch(void* const* d_in, const int* in_sizes, int n_in,
                              void* d_out, int out_size)
{
    // order: class_capsules, W, b, point_idx, segment_ids, num_segments
    const float4* feats4    = (const float4*)d_in[0];
    const float*  Wmat      = (const float*) d_in[1];
    const float*  bias      = (const float*) d_in[2];
    const int*    point_idx = (const int*)   d_in[3];
    const int*    seg_ids   = (const int*)   d_in[4];
    const int     P         = in_sizes[3];
    const int     nrows     = in_sizes[0] / D_FEAT;
    const int     NI        = out_size / NC_OUT;
    float* out = (float*)d_out;

    const int projBlocks = (nrows + P1_ROWS - 1) / P1_ROWS;

    proj_and_offsets_kernel<<<projBlocks + OFF_BLOCKS, P1_THREADS>>>(
        feats4, Wmat, seg_ids, P, NI, nrows, projBlocks);

    pool_head_kernel<<<NI, P2_THREADS>>>(point_idx, bias, out);
}